// round 1
// baseline (speedup 1.0000x reference)
#include <cuda_runtime.h>

#define H 128
#define CAP 128
#define NMAX 50000
#define EMAX 600000
#define AVGLOG 2.8332133440562162f   // ln(17)

// ---------------- scratch (static device globals; no allocation) ----------------
static __device__ float g_h[(size_t)EMAX * H];        // per-edge message h [E,128]
static __device__ float g_A[(size_t)NMAX * H];        // x @ Wpre[0:H]    (dst part)
static __device__ float g_B[(size_t)NMAX * H];        // x @ Wpre[H:2H]   (src part)
static __device__ float g_agg[(size_t)NMAX * 4 * H];  // [mean|max|min|std] per node
static __device__ float g_s1[NMAX];
static __device__ float g_s2[NMAX];
static __device__ float g_outbuf[(size_t)NMAX * H];   // pre-BN node output
static __device__ float g_C[(size_t)NMAX * H];        // x_new @ W1[0:H] + b1 (src part)
static __device__ float g_D[(size_t)NMAX * H];        // x_new @ W1[H:2H]     (dst part)
static __device__ float g_Wc[H * H];                  // We @ Wpre[2H:3H]
static __device__ float g_c0[H];                      // bpre + be @ Wpre[2H:3H]
static __device__ float g_Wpl[13 * H * H];            // Wpost @ Wlin
static __device__ float g_bpl[H];                     // bpost @ Wlin + blin
static __device__ int   g_deg[NMAX];
static __device__ int   g_eid[(size_t)NMAX * CAP];
static __device__ float g_bnsum[2 * H];

// ---------------- helpers ----------------
__device__ __forceinline__ void fma16(float (&acc)[4][4],
                                      float a0, float a1, float a2, float a3,
                                      float4 w) {
    acc[0][0] += a0 * w.x; acc[0][1] += a0 * w.y; acc[0][2] += a0 * w.z; acc[0][3] += a0 * w.w;
    acc[1][0] += a1 * w.x; acc[1][1] += a1 * w.y; acc[1][2] += a1 * w.z; acc[1][3] += a1 * w.w;
    acc[2][0] += a2 * w.x; acc[2][1] += a2 * w.y; acc[2][2] += a2 * w.z; acc[2][3] += a2 * w.w;
    acc[3][0] += a3 * w.x; acc[3][1] += a3 * w.y; acc[3][2] += a3 * w.z; acc[3][3] += a3 * w.w;
}

// ---------------- weight prep ----------------
__global__ void prep_Wc(const float* __restrict__ We, const float* __restrict__ be,
                        const float* __restrict__ Wpre, const float* __restrict__ bpre) {
    int j = threadIdx.x;
    int i = blockIdx.x;
    const float* W3 = Wpre + 2 * H * H;
    if (i < H) {
        float s = 0.f;
        for (int k = 0; k < H; k++) s += We[i * H + k] * W3[k * H + j];
        g_Wc[i * H + j] = s;
    } else {
        float s = bpre[j];
        for (int k = 0; k < H; k++) s += be[k] * W3[k * H + j];
        g_c0[j] = s;
    }
}

__global__ void prep_Wpl(const float* __restrict__ Wpost, const float* __restrict__ bpost,
                         const float* __restrict__ Wlin, const float* __restrict__ blin) {
    int j = threadIdx.x;
    int r = blockIdx.x;
    if (r < 13 * H) {
        float s = 0.f;
        for (int k = 0; k < H; k++) s += Wpost[(size_t)r * H + k] * Wlin[k * H + j];
        g_Wpl[(size_t)r * H + j] = s;
    } else {
        float s = blin[j];
        for (int k = 0; k < H; k++) s += bpost[k] * Wlin[k * H + j];
        g_bpl[j] = s;
    }
}

__global__ void zero_kernel(int N) {
    int i = blockIdx.x * blockDim.x + threadIdx.x;
    if (i < N) g_deg[i] = 0;
    if (i < 2 * H) g_bnsum[i] = 0.f;
}

// ---------------- generic SIMT GEMM: C[M,128] (+)= rowscale ⊙ (A[M,K] @ W[K,128]) + bias ----------------
__global__ __launch_bounds__(256) void sgemm128(
    float* __restrict__ C, const float* __restrict__ A, const float* __restrict__ W,
    int M, int K, const float* __restrict__ bias, const float* __restrict__ rowscale,
    int accum) {
    __shared__ float As[32][32];
    __shared__ float Ws[32][H];
    const int tid = threadIdx.x;
    const int rg = tid >> 5, cg = tid & 31;
    const int row0 = blockIdx.x * 32;
    float acc[4][4];
#pragma unroll
    for (int i = 0; i < 4; i++)
#pragma unroll
        for (int j = 0; j < 4; j++) acc[i][j] = 0.f;

    for (int k0 = 0; k0 < K; k0 += 32) {
        {   // A tile: 256 float4
            int r = tid >> 3, c4 = tid & 7;
            int row = row0 + r;
            float4 v = make_float4(0.f, 0.f, 0.f, 0.f);
            if (row < M) v = *(const float4*)&A[(size_t)row * K + k0 + c4 * 4];
            *(float4*)&As[r][c4 * 4] = v;
        }
#pragma unroll
        for (int t = 0; t < 4; t++) {  // W tile: 1024 float4
            int i = tid + t * 256;
            int r = i >> 5, c4 = i & 31;
            *(float4*)&Ws[r][c4 * 4] = *(const float4*)&W[(size_t)(k0 + r) * H + c4 * 4];
        }
        __syncthreads();
#pragma unroll
        for (int kk = 0; kk < 32; kk++) {
            float4 w = *(const float4*)&Ws[kk][cg * 4];
            fma16(acc, As[rg * 4 + 0][kk], As[rg * 4 + 1][kk],
                       As[rg * 4 + 2][kk], As[rg * 4 + 3][kk], w);
        }
        __syncthreads();
    }
#pragma unroll
    for (int i = 0; i < 4; i++) {
        int row = row0 + rg * 4 + i;
        if (row >= M) break;
        float4 v = make_float4(acc[i][0], acc[i][1], acc[i][2], acc[i][3]);
        float* Cp = &C[(size_t)row * H + cg * 4];
        if (accum) {
            float rs = rowscale ? rowscale[row] : 1.f;
            float4 o = *(const float4*)Cp;
            o.x += rs * v.x; o.y += rs * v.y; o.z += rs * v.z; o.w += rs * v.w;
            *(float4*)Cp = o;
        } else {
            if (bias) {
                v.x += bias[cg * 4 + 0]; v.y += bias[cg * 4 + 1];
                v.z += bias[cg * 4 + 2]; v.w += bias[cg * 4 + 3];
            }
            *(float4*)Cp = v;
        }
    }
}

// ---------------- edge message GEMM: h = edge_attr @ Wc + A[dst] + B[src] + c0 ----------------
__global__ __launch_bounds__(256) void edge_h_kernel(
    const float* __restrict__ ea, const int* __restrict__ src,
    const int* __restrict__ dst, int E) {
    __shared__ float As[32][32];
    __shared__ float Ws[32][H];
    const int tid = threadIdx.x;
    const int rg = tid >> 5, cg = tid & 31;
    const long long row0 = (long long)blockIdx.x * 32;
    float acc[4][4];
#pragma unroll
    for (int i = 0; i < 4; i++)
#pragma unroll
        for (int j = 0; j < 4; j++) acc[i][j] = 0.f;

    for (int k0 = 0; k0 < H; k0 += 32) {
        {
            int r = tid >> 3, c4 = tid & 7;
            long long row = row0 + r;
            float4 v = make_float4(0.f, 0.f, 0.f, 0.f);
            if (row < E) v = *(const float4*)&ea[row * H + k0 + c4 * 4];
            *(float4*)&As[r][c4 * 4] = v;
        }
#pragma unroll
        for (int t = 0; t < 4; t++) {
            int i = tid + t * 256;
            int r = i >> 5, c4 = i & 31;
            *(float4*)&Ws[r][c4 * 4] = *(const float4*)&g_Wc[(k0 + r) * H + c4 * 4];
        }
        __syncthreads();
#pragma unroll
        for (int kk = 0; kk < 32; kk++) {
            float4 w = *(const float4*)&Ws[kk][cg * 4];
            fma16(acc, As[rg * 4 + 0][kk], As[rg * 4 + 1][kk],
                       As[rg * 4 + 2][kk], As[rg * 4 + 3][kk], w);
        }
        __syncthreads();
    }
#pragma unroll
    for (int i = 0; i < 4; i++) {
        long long row = row0 + rg * 4 + i;
        if (row >= E) break;
        int d = dst[row], s = src[row];
        float4 av = *(const float4*)&g_A[(size_t)d * H + cg * 4];
        float4 bv = *(const float4*)&g_B[(size_t)s * H + cg * 4];
        float4 cv = *(const float4*)&g_c0[cg * 4];
        float4 o;
        o.x = acc[i][0] + av.x + bv.x + cv.x;
        o.y = acc[i][1] + av.y + bv.y + cv.y;
        o.z = acc[i][2] + av.z + bv.z + cv.z;
        o.w = acc[i][3] + av.w + bv.w + cv.w;
        *(float4*)&g_h[row * H + cg * 4] = o;
    }
}

// ---------------- degree count + bucket fill ----------------
__global__ void count_fill(const int* __restrict__ dst, int E) {
    int stride = gridDim.x * blockDim.x;
    for (int e = blockIdx.x * blockDim.x + threadIdx.x; e < E; e += stride) {
        int d = dst[e];
        int pos = atomicAdd(&g_deg[d], 1);
        if (pos < CAP) g_eid[(size_t)d * CAP + pos] = e;
    }
}

// ---------------- warp-per-node aggregation: mean/max/min/std + degree scalers ----------------
__global__ __launch_bounds__(256) void agg_kernel(int N) {
    int warp = (blockIdx.x * blockDim.x + threadIdx.x) >> 5;
    int lane = threadIdx.x & 31;
    if (warp >= N) return;
    int n = warp;
    int d = g_deg[n];
    int dc = d < CAP ? d : CAP;
    float4 s  = make_float4(0.f, 0.f, 0.f, 0.f);
    float4 s2 = make_float4(0.f, 0.f, 0.f, 0.f);
    float4 mx = make_float4(-3.4e38f, -3.4e38f, -3.4e38f, -3.4e38f);
    float4 mn = make_float4( 3.4e38f,  3.4e38f,  3.4e38f,  3.4e38f);
    const float4* h4 = (const float4*)g_h;
    for (int j = 0; j < dc; j++) {
        int e = g_eid[(size_t)n * CAP + j];
        float4 v = h4[(size_t)e * 32 + lane];
        s.x += v.x; s.y += v.y; s.z += v.z; s.w += v.w;
        s2.x += v.x * v.x; s2.y += v.y * v.y; s2.z += v.z * v.z; s2.w += v.w * v.w;
        mx.x = fmaxf(mx.x, v.x); mx.y = fmaxf(mx.y, v.y); mx.z = fmaxf(mx.z, v.z); mx.w = fmaxf(mx.w, v.w);
        mn.x = fminf(mn.x, v.x); mn.y = fminf(mn.y, v.y); mn.z = fminf(mn.z, v.z); mn.w = fminf(mn.w, v.w);
    }
    float degc = fmaxf((float)d, 1.f);
    float inv = 1.f / degc;
    float4 mean = make_float4(s.x * inv, s.y * inv, s.z * inv, s.w * inv);
    float4 m2   = make_float4(s2.x * inv, s2.y * inv, s2.z * inv, s2.w * inv);
    float4 sd;
    sd.x = sqrtf(fmaxf(m2.x - mean.x * mean.x, 0.f) + 1e-5f);
    sd.y = sqrtf(fmaxf(m2.y - mean.y * mean.y, 0.f) + 1e-5f);
    sd.z = sqrtf(fmaxf(m2.z - mean.z * mean.z, 0.f) + 1e-5f);
    sd.w = sqrtf(fmaxf(m2.w - mean.w * mean.w, 0.f) + 1e-5f);
    if (d == 0) {
        mx = make_float4(0.f, 0.f, 0.f, 0.f);
        mn = make_float4(0.f, 0.f, 0.f, 0.f);
    }
    float4* aggp = (float4*)&g_agg[(size_t)n * 4 * H];
    aggp[lane] = mean;          // cols 0..127   : mean
    aggp[32 + lane] = mx;       // cols 128..255 : max
    aggp[64 + lane] = mn;       // cols 256..383 : min
    aggp[96 + lane] = sd;       // cols 384..511 : std
    if (lane == 0) {
        float ld = logf(degc + 1.f);
        g_s1[n] = ld / AVGLOG;
        g_s2[n] = AVGLOG / ld;
    }
}

// ---------------- BatchNorm statistics + finalize ----------------
__global__ void bn_stats(int N) {
    int c = threadIdx.x;       // 128 channels
    int r0 = blockIdx.x * 256;
    float s = 0.f, s2 = 0.f;
    for (int i = 0; i < 256; i++) {
        int r = r0 + i;
        if (r < N) {
            float v = g_outbuf[(size_t)r * H + c];
            s += v; s2 += v * v;
        }
    }
    atomicAdd(&g_bnsum[c], s);
    atomicAdd(&g_bnsum[H + c], s2);
}

__global__ void bn_finalize(float* __restrict__ xnew, const float* __restrict__ x,
                            const float* __restrict__ gamma, const float* __restrict__ beta,
                            int N) {
    size_t total = (size_t)N * H;
    size_t stride = (size_t)gridDim.x * blockDim.x;
    float invN = 1.f / (float)N;
    for (size_t i = (size_t)blockIdx.x * blockDim.x + threadIdx.x; i < total; i += stride) {
        int c = (int)(i & (H - 1));
        float mu = g_bnsum[c] * invN;
        float var = g_bnsum[H + c] * invN - mu * mu;
        float inv = rsqrtf(var + 1e-5f);
        float v = (g_outbuf[i] - mu) * inv * gamma[c] + beta[c];
        xnew[i] = 0.5f * (x[i] + fmaxf(v, 0.f));
    }
}

// ---------------- fused edge update: e_new = ea + 0.5*(relu(ea@W1c + C[src] + D[dst]) @ W2 + b2) ----------------
__global__ __launch_bounds__(256) void edge_update(
    float* __restrict__ eout, const float* __restrict__ ea,
    const float* __restrict__ W1c, const float* __restrict__ W2,
    const float* __restrict__ b2, const int* __restrict__ src,
    const int* __restrict__ dst, int E) {
    __shared__ float Es[32][H];
    __shared__ float Ts[32][H];
    __shared__ float Ws[32][H];
    const int tid = threadIdx.x;
    const int rg = tid >> 5, cg = tid & 31;
    const long long row0 = (long long)blockIdx.x * 32;

#pragma unroll
    for (int t = 0; t < 4; t++) {
        int i = tid + t * 256;
        int r = i >> 5, c4 = i & 31;
        long long row = row0 + r;
        float4 v = make_float4(0.f, 0.f, 0.f, 0.f);
        if (row < E) v = *(const float4*)&ea[row * H + c4 * 4];
        *(float4*)&Es[r][c4 * 4] = v;
    }
    float acc[4][4];
#pragma unroll
    for (int i = 0; i < 4; i++)
#pragma unroll
        for (int j = 0; j < 4; j++) acc[i][j] = 0.f;

    // ---- phase 1: t = relu(Es @ W1c + C[src] + D[dst])  (b1 folded into C) ----
    for (int k0 = 0; k0 < H; k0 += 32) {
#pragma unroll
        for (int t = 0; t < 4; t++) {
            int i = tid + t * 256;
            int r = i >> 5, c4 = i & 31;
            *(float4*)&Ws[r][c4 * 4] = *(const float4*)&W1c[(size_t)(k0 + r) * H + c4 * 4];
        }
        __syncthreads();
#pragma unroll
        for (int kk = 0; kk < 32; kk++) {
            float4 w = *(const float4*)&Ws[kk][cg * 4];
            fma16(acc, Es[rg * 4 + 0][k0 + kk], Es[rg * 4 + 1][k0 + kk],
                       Es[rg * 4 + 2][k0 + kk], Es[rg * 4 + 3][k0 + kk], w);
        }
        __syncthreads();
    }
#pragma unroll
    for (int i = 0; i < 4; i++) {
        long long row = row0 + rg * 4 + i;
        int s = 0, d = 0;
        if (row < E) { s = src[row]; d = dst[row]; }
        float4 cv = *(const float4*)&g_C[(size_t)s * H + cg * 4];
        float4 dv = *(const float4*)&g_D[(size_t)d * H + cg * 4];
        float4 t4;
        t4.x = fmaxf(acc[i][0] + cv.x + dv.x, 0.f);
        t4.y = fmaxf(acc[i][1] + cv.y + dv.y, 0.f);
        t4.z = fmaxf(acc[i][2] + cv.z + dv.z, 0.f);
        t4.w = fmaxf(acc[i][3] + cv.w + dv.w, 0.f);
        *(float4*)&Ts[rg * 4 + i][cg * 4] = t4;
    }
#pragma unroll
    for (int i = 0; i < 4; i++)
#pragma unroll
        for (int j = 0; j < 4; j++) acc[i][j] = 0.f;

    // ---- phase 2: e_new = Es + 0.5*(Ts @ W2 + b2) ----
    for (int k0 = 0; k0 < H; k0 += 32) {
#pragma unroll
        for (int t = 0; t < 4; t++) {
            int i = tid + t * 256;
            int r = i >> 5, c4 = i & 31;
            *(float4*)&Ws[r][c4 * 4] = *(const float4*)&W2[(size_t)(k0 + r) * H + c4 * 4];
        }
        __syncthreads();
#pragma unroll
        for (int kk = 0; kk < 32; kk++) {
            float4 w = *(const float4*)&Ws[kk][cg * 4];
            fma16(acc, Ts[rg * 4 + 0][k0 + kk], Ts[rg * 4 + 1][k0 + kk],
                       Ts[rg * 4 + 2][k0 + kk], Ts[rg * 4 + 3][k0 + kk], w);
        }
        __syncthreads();
    }
#pragma unroll
    for (int i = 0; i < 4; i++) {
        long long row = row0 + rg * 4 + i;
        if (row >= E) break;
        float4 e4 = *(const float4*)&Es[rg * 4 + i][cg * 4];
        float4 b4 = *(const float4*)&b2[cg * 4];
        float4 o;
        o.x = e4.x + 0.5f * (acc[i][0] + b4.x);
        o.y = e4.y + 0.5f * (acc[i][1] + b4.y);
        o.z = e4.z + 0.5f * (acc[i][2] + b4.z);
        o.w = e4.w + 0.5f * (acc[i][3] + b4.w);
        *(float4*)&eout[row * H + cg * 4] = o;
    }
}

// ---------------- launch ----------------
extern "C" void kernel_launch(void* const* d_in, const int* in_sizes, int n_in,
                              void* d_out, int out_size) {
    const float* x     = (const float*)d_in[0];
    const float* ea    = (const float*)d_in[1];
    const float* We    = (const float*)d_in[2];
    const float* be    = (const float*)d_in[3];
    const float* Wpre  = (const float*)d_in[4];
    const float* bpre  = (const float*)d_in[5];
    const float* Wpost = (const float*)d_in[6];
    const float* bpost = (const float*)d_in[7];
    const float* Wlin  = (const float*)d_in[8];
    const float* blin  = (const float*)d_in[9];
    const float* bn_g  = (const float*)d_in[10];
    const float* bn_b  = (const float*)d_in[11];
    const float* W1    = (const float*)d_in[12];
    const float* b1    = (const float*)d_in[13];
    const float* W2    = (const float*)d_in[14];
    const float* b2    = (const float*)d_in[15];
    const int*   ei    = (const int*)d_in[16];

    int N = in_sizes[0] / H;
    int E = in_sizes[1] / H;
    const int* src = ei;
    const int* dst = ei + E;
    float* xnew = (float*)d_out;
    float* enew = (float*)d_out + (size_t)N * H;

    float *pA, *pB, *pOut, *pAgg, *pWpl, *pbpl, *pS1, *pS2, *pC, *pD;
    cudaGetSymbolAddress((void**)&pA, g_A);
    cudaGetSymbolAddress((void**)&pB, g_B);
    cudaGetSymbolAddress((void**)&pOut, g_outbuf);
    cudaGetSymbolAddress((void**)&pAgg, g_agg);
    cudaGetSymbolAddress((void**)&pWpl, g_Wpl);
    cudaGetSymbolAddress((void**)&pbpl, g_bpl);
    cudaGetSymbolAddress((void**)&pS1, g_s1);
    cudaGetSymbolAddress((void**)&pS2, g_s2);
    cudaGetSymbolAddress((void**)&pC, g_C);
    cudaGetSymbolAddress((void**)&pD, g_D);

    int gN = (N + 31) / 32;
    int gE = (E + 31) / 32;

    prep_Wc<<<H + 1, H>>>(We, be, Wpre, bpre);
    prep_Wpl<<<13 * H + 1, H>>>(Wpost, bpost, Wlin, blin);
    zero_kernel<<<(N + 255) / 256, 256>>>(N);

    // A = x @ Wpre[0:H] (dst part), B = x @ Wpre[H:2H] (src part)
    sgemm128<<<gN, 256>>>(pA, x, Wpre,          N, H, nullptr, nullptr, 0);
    sgemm128<<<gN, 256>>>(pB, x, Wpre + H * H,  N, H, nullptr, nullptr, 0);

    count_fill<<<256, 256>>>(dst, E);
    edge_h_kernel<<<gE, 256>>>(ea, src, dst, E);
    agg_kernel<<<(N + 7) / 8, 256>>>(N);

    // out = x@Wpl0 + agg@WplA + s1*(agg@WplB) + s2*(agg@WplC) + bpl
    sgemm128<<<gN, 256>>>(pOut, x,    pWpl,             N, H,     pbpl,    nullptr, 0);
    sgemm128<<<gN, 256>>>(pOut, pAgg, pWpl + 1 * H * H, N, 4 * H, nullptr, nullptr, 1);
    sgemm128<<<gN, 256>>>(pOut, pAgg, pWpl + 5 * H * H, N, 4 * H, nullptr, pS1,     1);
    sgemm128<<<gN, 256>>>(pOut, pAgg, pWpl + 9 * H * H, N, 4 * H, nullptr, pS2,     1);

    bn_stats<<<(N + 255) / 256, H>>>(N);
    bn_finalize<<<2048, 256>>>(xnew, x, bn_g, bn_b, N);

    // C = x_new @ W1[0:H] + b1 (src part), D = x_new @ W1[H:2H] (dst part)
    sgemm128<<<gN, 256>>>(pC, xnew, W1,         N, H, b1,      nullptr, 0);
    sgemm128<<<gN, 256>>>(pD, xnew, W1 + H * H, N, H, nullptr, nullptr, 0);

    edge_update<<<gE, 256>>>(enew, ea, W1 + 2 * H * H, W2, b2, src, dst, E);
}

// round 11
// speedup vs baseline: 1.1984x; 1.1984x over previous
#include <cuda_runtime.h>
#include <stdint.h>
#include <cstdint>

#define H 128
#define CAP 128
#define NMAX 50000
#define EMAX 600000
#define AVGLOG 2.8332133440562162f   // ln(17)

// ---------------- scratch (static device globals; no allocation) ----------------
static __device__ float g_h[(size_t)EMAX * H];        // per-edge message h [E,128]
static __device__ float g_A[(size_t)NMAX * H];        // x @ Wpre[0:H]    (dst part)
static __device__ float g_B[(size_t)NMAX * H];        // x @ Wpre[H:2H]   (src part)
static __device__ float g_agg[(size_t)NMAX * 4 * H];  // [mean|max|min|std] per node
static __device__ float g_s1[NMAX];
static __device__ float g_s2[NMAX];
static __device__ float g_outbuf[(size_t)NMAX * H];   // pre-BN node output
static __device__ float g_C[(size_t)NMAX * H];        // x_new @ W1[0:H] + b1 (src part)
static __device__ float g_D[(size_t)NMAX * H];        // x_new @ W1[H:2H]     (dst part)
static __device__ float g_Wc[H * H];                  // We @ Wpre[2H:3H]
static __device__ float g_c0[H];                      // bpre + be @ Wpre[2H:3H]
static __device__ float g_Wpl[13 * H * H];            // Wpost @ Wlin
static __device__ float g_bpl[H];                     // bpost @ Wlin + blin
static __device__ int   g_deg[NMAX];
static __device__ int   g_eid[(size_t)NMAX * CAP];
static __device__ float g_bnsum[2 * H];

// ---------------- cp.async helpers ----------------
__device__ __forceinline__ void cp16(uint32_t dst, const void* src, bool pred) {
    int sz = pred ? 16 : 0;
    asm volatile("cp.async.cg.shared.global [%0], [%1], 16, %2;\n"
                 :: "r"(dst), "l"(src), "r"(sz));
}
__device__ __forceinline__ void cpa_commit() {
    asm volatile("cp.async.commit_group;\n" ::: "memory");
}
__device__ __forceinline__ void cpa_wait0() {
    asm volatile("cp.async.wait_group 0;\n" ::: "memory");
}
__device__ __forceinline__ void cpa_wait1() {
    asm volatile("cp.async.wait_group 1;\n" ::: "memory");
}

// ---------------- weight prep ----------------
__global__ void prep_Wc(const float* __restrict__ We, const float* __restrict__ be,
                        const float* __restrict__ Wpre, const float* __restrict__ bpre) {
    int j = threadIdx.x;
    int i = blockIdx.x;
    const float* W3 = Wpre + 2 * H * H;
    if (i < H) {
        float s = 0.f;
        for (int k = 0; k < H; k++) s += We[i * H + k] * W3[k * H + j];
        g_Wc[i * H + j] = s;
    } else {
        float s = bpre[j];
        for (int k = 0; k < H; k++) s += be[k] * W3[k * H + j];
        g_c0[j] = s;
    }
}

__global__ void prep_Wpl(const float* __restrict__ Wpost, const float* __restrict__ bpost,
                         const float* __restrict__ Wlin, const float* __restrict__ blin) {
    int j = threadIdx.x;
    int r = blockIdx.x;
    if (r < 13 * H) {
        float s = 0.f;
        for (int k = 0; k < H; k++) s += Wpost[(size_t)r * H + k] * Wlin[k * H + j];
        g_Wpl[(size_t)r * H + j] = s;
    } else {
        float s = blin[j];
        for (int k = 0; k < H; k++) s += bpost[k] * Wlin[k * H + j];
        g_bpl[j] = s;
    }
}

__global__ void zero_kernel(int N) {
    int i = blockIdx.x * blockDim.x + threadIdx.x;
    if (i < N) g_deg[i] = 0;
    if (i < 2 * H) g_bnsum[i] = 0.f;
}

// ---------------- 64x128 tiled GEMM, 8x4 micro-tile, cp.async double buffer ----------------
// C[M,128] (+)= rowscale ⊙ (A[M,K] @ W[K,128]) + bias
__global__ __launch_bounds__(256) void sgemm64(
    float* __restrict__ C, const float* __restrict__ A, const float* __restrict__ W,
    int M, int K, const float* __restrict__ bias, const float* __restrict__ rowscale,
    int accum) {
    __shared__ float As[2][64 * 32];   // 16 KB
    __shared__ float Ws[2][32 * 128];  // 32 KB  (total 48 KB)
    const int tid = threadIdx.x;
    const int cg = tid & 31;
    const int rg = tid >> 5;
    const int row0 = blockIdx.x * 64;

    const uint32_t sA0 = (uint32_t)__cvta_generic_to_shared(&As[0][0]);
    const uint32_t sW0 = (uint32_t)__cvta_generic_to_shared(&Ws[0][0]);

    auto loadA = [&](int k0, int b) {
#pragma unroll
        for (int j = 0; j < 2; j++) {
            int f = tid + j * 256;           // float4 id, 0..511
            int r = f >> 3, c4 = f & 7;
            int row = row0 + r;
            const float* src = &A[(size_t)row * K + k0 + c4 * 4];
            uint32_t dst = sA0 + (uint32_t)(b * (64 * 32) + r * 32 + c4 * 4) * 4u;
            cp16(dst, src, row < M);
        }
    };
    auto loadW = [&](int k0, int b) {
#pragma unroll
        for (int j = 0; j < 4; j++) {
            int f = tid + j * 256;           // float4 id, 0..1023
            int r = f >> 5, c4 = f & 31;
            const float* src = &W[(size_t)(k0 + r) * 128 + c4 * 4];
            uint32_t dst = sW0 + (uint32_t)(b * (32 * 128) + r * 128 + c4 * 4) * 4u;
            cp16(dst, src, true);
        }
    };

    float acc[8][4];
#pragma unroll
    for (int i = 0; i < 8; i++)
#pragma unroll
        for (int j = 0; j < 4; j++) acc[i][j] = 0.f;

    loadA(0, 0); loadW(0, 0); cpa_commit();
    int b = 0;
    for (int k0 = 0; k0 < K; k0 += 32, b ^= 1) {
        bool nxt = (k0 + 32) < K;
        if (nxt) { loadA(k0 + 32, b ^ 1); loadW(k0 + 32, b ^ 1); cpa_commit(); }
        if (nxt) cpa_wait1(); else cpa_wait0();
        __syncthreads();
        const float* as = &As[b][0];
        const float* ws = &Ws[b][0];
#pragma unroll
        for (int kk = 0; kk < 32; kk++) {
            float4 w = *(const float4*)&ws[kk * 128 + cg * 4];
            float a[8];
#pragma unroll
            for (int i = 0; i < 8; i++) a[i] = as[(rg * 8 + i) * 32 + kk];
#pragma unroll
            for (int i = 0; i < 8; i++) {
                acc[i][0] += a[i] * w.x; acc[i][1] += a[i] * w.y;
                acc[i][2] += a[i] * w.z; acc[i][3] += a[i] * w.w;
            }
        }
        __syncthreads();
    }
#pragma unroll
    for (int i = 0; i < 8; i++) {
        int row = row0 + rg * 8 + i;
        if (row >= M) break;
        float4 v = make_float4(acc[i][0], acc[i][1], acc[i][2], acc[i][3]);
        float* Cp = &C[(size_t)row * 128 + cg * 4];
        if (accum) {
            float rs = rowscale ? rowscale[row] : 1.f;
            float4 o = *(const float4*)Cp;
            o.x += rs * v.x; o.y += rs * v.y; o.z += rs * v.z; o.w += rs * v.w;
            *(float4*)Cp = o;
        } else {
            if (bias) {
                v.x += bias[cg * 4 + 0]; v.y += bias[cg * 4 + 1];
                v.z += bias[cg * 4 + 2]; v.w += bias[cg * 4 + 3];
            }
            *(float4*)Cp = v;
        }
    }
}

// ---------------- edge message GEMM: h = edge_attr @ Wc + A[dst] + B[src] + c0 ----------------
__global__ __launch_bounds__(256) void edge_h_kernel(
    const float* __restrict__ ea, const int* __restrict__ src,
    const int* __restrict__ dst, int E) {
    __shared__ float As[2][64 * 32];
    __shared__ float Ws[2][32 * 128];
    const int tid = threadIdx.x;
    const int cg = tid & 31;
    const int rg = tid >> 5;
    const long long row0 = (long long)blockIdx.x * 64;

    const uint32_t sA0 = (uint32_t)__cvta_generic_to_shared(&As[0][0]);
    const uint32_t sW0 = (uint32_t)__cvta_generic_to_shared(&Ws[0][0]);

    auto loadA = [&](int k0, int b) {
#pragma unroll
        for (int j = 0; j < 2; j++) {
            int f = tid + j * 256;
            int r = f >> 3, c4 = f & 7;
            long long row = row0 + r;
            const float* s = &ea[row * H + k0 + c4 * 4];
            uint32_t dstp = sA0 + (uint32_t)(b * (64 * 32) + r * 32 + c4 * 4) * 4u;
            cp16(dstp, s, row < E);
        }
    };
    auto loadW = [&](int k0, int b) {
#pragma unroll
        for (int j = 0; j < 4; j++) {
            int f = tid + j * 256;
            int r = f >> 5, c4 = f & 31;
            const float* s = &g_Wc[(k0 + r) * 128 + c4 * 4];
            uint32_t dstp = sW0 + (uint32_t)(b * (32 * 128) + r * 128 + c4 * 4) * 4u;
            cp16(dstp, s, true);
        }
    };

    float acc[8][4];
#pragma unroll
    for (int i = 0; i < 8; i++)
#pragma unroll
        for (int j = 0; j < 4; j++) acc[i][j] = 0.f;

    loadA(0, 0); loadW(0, 0); cpa_commit();
    int b = 0;
    for (int k0 = 0; k0 < H; k0 += 32, b ^= 1) {
        bool nxt = (k0 + 32) < H;
        if (nxt) { loadA(k0 + 32, b ^ 1); loadW(k0 + 32, b ^ 1); cpa_commit(); }
        if (nxt) cpa_wait1(); else cpa_wait0();
        __syncthreads();
        const float* as = &As[b][0];
        const float* ws = &Ws[b][0];
#pragma unroll
        for (int kk = 0; kk < 32; kk++) {
            float4 w = *(const float4*)&ws[kk * 128 + cg * 4];
            float a[8];
#pragma unroll
            for (int i = 0; i < 8; i++) a[i] = as[(rg * 8 + i) * 32 + kk];
#pragma unroll
            for (int i = 0; i < 8; i++) {
                acc[i][0] += a[i] * w.x; acc[i][1] += a[i] * w.y;
                acc[i][2] += a[i] * w.z; acc[i][3] += a[i] * w.w;
            }
        }
        __syncthreads();
    }
    float4 cv = *(const float4*)&g_c0[cg * 4];
#pragma unroll
    for (int i = 0; i < 8; i++) {
        long long row = row0 + rg * 8 + i;
        if (row >= E) break;
        int d = dst[row], s = src[row];
        float4 av = *(const float4*)&g_A[(size_t)d * H + cg * 4];
        float4 bv = *(const float4*)&g_B[(size_t)s * H + cg * 4];
        float4 o;
        o.x = acc[i][0] + av.x + bv.x + cv.x;
        o.y = acc[i][1] + av.y + bv.y + cv.y;
        o.z = acc[i][2] + av.z + bv.z + cv.z;
        o.w = acc[i][3] + av.w + bv.w + cv.w;
        *(float4*)&g_h[row * H + cg * 4] = o;
    }
}

// ---------------- degree count + bucket fill ----------------
__global__ void count_fill(const int* __restrict__ dst, int E) {
    int stride = gridDim.x * blockDim.x;
    for (int e = blockIdx.x * blockDim.x + threadIdx.x; e < E; e += stride) {
        int d = dst[e];
        int pos = atomicAdd(&g_deg[d], 1);
        if (pos < CAP) g_eid[(size_t)d * CAP + pos] = e;
    }
}

// ---------------- warp-per-node aggregation ----------------
__global__ __launch_bounds__(256) void agg_kernel(int N) {
    int warp = (blockIdx.x * blockDim.x + threadIdx.x) >> 5;
    int lane = threadIdx.x & 31;
    if (warp >= N) return;
    int n = warp;
    int d = g_deg[n];
    int dc = d < CAP ? d : CAP;
    float4 s  = make_float4(0.f, 0.f, 0.f, 0.f);
    float4 s2 = make_float4(0.f, 0.f, 0.f, 0.f);
    float4 mx = make_float4(-3.4e38f, -3.4e38f, -3.4e38f, -3.4e38f);
    float4 mn = make_float4( 3.4e38f,  3.4e38f,  3.4e38f,  3.4e38f);
    const float4* h4 = (const float4*)g_h;
    for (int j = 0; j < dc; j++) {
        int e = g_eid[(size_t)n * CAP + j];
        float4 v = h4[(size_t)e * 32 + lane];
        s.x += v.x; s.y += v.y; s.z += v.z; s.w += v.w;
        s2.x += v.x * v.x; s2.y += v.y * v.y; s2.z += v.z * v.z; s2.w += v.w * v.w;
        mx.x = fmaxf(mx.x, v.x); mx.y = fmaxf(mx.y, v.y); mx.z = fmaxf(mx.z, v.z); mx.w = fmaxf(mx.w, v.w);
        mn.x = fminf(mn.x, v.x); mn.y = fminf(mn.y, v.y); mn.z = fminf(mn.z, v.z); mn.w = fminf(mn.w, v.w);
    }
    float degc = fmaxf((float)d, 1.f);
    float inv = 1.f / degc;
    float4 mean = make_float4(s.x * inv, s.y * inv, s.z * inv, s.w * inv);
    float4 m2   = make_float4(s2.x * inv, s2.y * inv, s2.z * inv, s2.w * inv);
    float4 sd;
    sd.x = sqrtf(fmaxf(m2.x - mean.x * mean.x, 0.f) + 1e-5f);
    sd.y = sqrtf(fmaxf(m2.y - mean.y * mean.y, 0.f) + 1e-5f);
    sd.z = sqrtf(fmaxf(m2.z - mean.z * mean.z, 0.f) + 1e-5f);
    sd.w = sqrtf(fmaxf(m2.w - mean.w * mean.w, 0.f) + 1e-5f);
    if (d == 0) {
        mx = make_float4(0.f, 0.f, 0.f, 0.f);
        mn = make_float4(0.f, 0.f, 0.f, 0.f);
    }
    float4* aggp = (float4*)&g_agg[(size_t)n * 4 * H];
    aggp[lane] = mean;
    aggp[32 + lane] = mx;
    aggp[64 + lane] = mn;
    aggp[96 + lane] = sd;
    if (lane == 0) {
        float ld = logf(degc + 1.f);
        g_s1[n] = ld / AVGLOG;
        g_s2[n] = AVGLOG / ld;
    }
}

// ---------------- BatchNorm statistics + finalize ----------------
__global__ void bn_stats(int N) {
    int c = threadIdx.x;
    int r0 = blockIdx.x * 256;
    float s = 0.f, s2 = 0.f;
    for (int i = 0; i < 256; i++) {
        int r = r0 + i;
        if (r < N) {
            float v = g_outbuf[(size_t)r * H + c];
            s += v; s2 += v * v;
        }
    }
    atomicAdd(&g_bnsum[c], s);
    atomicAdd(&g_bnsum[H + c], s2);
}

__global__ void bn_finalize(float* __restrict__ xnew, const float* __restrict__ x,
                            const float* __restrict__ gamma, const float* __restrict__ beta,
                            int N) {
    size_t total = (size_t)N * H;
    size_t stride = (size_t)gridDim.x * blockDim.x;
    float invN = 1.f / (float)N;
    for (size_t i = (size_t)blockIdx.x * blockDim.x + threadIdx.x; i < total; i += stride) {
        int c = (int)(i & (H - 1));
        float mu = g_bnsum[c] * invN;
        float var = g_bnsum[H + c] * invN - mu * mu;
        float inv = rsqrtf(var + 1e-5f);
        float v = (g_outbuf[i] - mu) * inv * gamma[c] + beta[c];
        xnew[i] = 0.5f * (x[i] + fmaxf(v, 0.f));
    }
}

// ---------------- fused edge update ----------------
// e_new = ea + 0.5*(relu(ea@W1c + C[src] + D[dst]) @ W2 + b2)
// 64-row tile resident in smem (Es reused as t-tile). W tiles 16 rows, double buffered.
__global__ __launch_bounds__(256) void edge_update(
    float* __restrict__ eout, const float* __restrict__ ea,
    const float* __restrict__ W1c, const float* __restrict__ W2,
    const float* __restrict__ b2, const int* __restrict__ src,
    const int* __restrict__ dst, int E) {
    __shared__ float Es[64 * 128];     // 32 KB (edge tile, then t tile)
    __shared__ float Ws[2][16 * 128];  // 16 KB (total 48 KB)
    const int tid = threadIdx.x;
    const int cg = tid & 31;
    const int rg = tid >> 5;
    const long long row0 = (long long)blockIdx.x * 64;

    const uint32_t sE0 = (uint32_t)__cvta_generic_to_shared(&Es[0]);
    const uint32_t sW0 = (uint32_t)__cvta_generic_to_shared(&Ws[0][0]);

    auto loadW = [&](const float* __restrict__ W, int k0, int b) {
#pragma unroll
        for (int j = 0; j < 2; j++) {
            int f = tid + j * 256;          // float4 id 0..511
            int r = f >> 5, c4 = f & 31;
            const float* s = &W[(size_t)(k0 + r) * 128 + c4 * 4];
            uint32_t dstp = sW0 + (uint32_t)(b * (16 * 128) + r * 128 + c4 * 4) * 4u;
            cp16(dstp, s, true);
        }
    };

    // load edge tile (8 float4 per thread)
#pragma unroll
    for (int j = 0; j < 8; j++) {
        int f = tid + j * 256;              // float4 id 0..2047
        int r = f >> 5, c4 = f & 31;
        long long row = row0 + r;
        const float* s = &ea[row * H + c4 * 4];
        uint32_t dstp = sE0 + (uint32_t)(r * 128 + c4 * 4) * 4u;
        cp16(dstp, s, row < E);
    }
    loadW(W1c, 0, 0);
    cpa_commit();

    float acc[8][4];
#pragma unroll
    for (int i = 0; i < 8; i++)
#pragma unroll
        for (int j = 0; j < 4; j++) acc[i][j] = 0.f;

    // ---- phase 1: t = relu(Es @ W1c + C[src] + D[dst]) ----
    int b = 0;
    for (int k0 = 0; k0 < H; k0 += 16, b ^= 1) {
        bool nxt = (k0 + 16) < H;
        if (nxt) { loadW(W1c, k0 + 16, b ^ 1); cpa_commit(); }
        if (nxt) cpa_wait1(); else cpa_wait0();
        __syncthreads();
        const float* ws = &Ws[b][0];
#pragma unroll
        for (int kk = 0; kk < 16; kk++) {
            float4 w = *(const float4*)&ws[kk * 128 + cg * 4];
            float a[8];
#pragma unroll
            for (int i = 0; i < 8; i++) a[i] = Es[(rg * 8 + i) * 128 + k0 + kk];
#pragma unroll
            for (int i = 0; i < 8; i++) {
                acc[i][0] += a[i] * w.x; acc[i][1] += a[i] * w.y;
                acc[i][2] += a[i] * w.z; acc[i][3] += a[i] * w.w;
            }
        }
        __syncthreads();
    }
    // epilogue 1: gather node terms, relu (registers only)
#pragma unroll
    for (int i = 0; i < 8; i++) {
        long long row = row0 + rg * 8 + i;
        int s = 0, d = 0;
        if (row < E) { s = src[row]; d = dst[row]; }
        float4 cv = *(const float4*)&g_C[(size_t)s * H + cg * 4];
        float4 dv = *(const float4*)&g_D[(size_t)d * H + cg * 4];
        acc[i][0] = fmaxf(acc[i][0] + cv.x + dv.x, 0.f);
        acc[i][1] = fmaxf(acc[i][1] + cv.y + dv.y, 0.f);
        acc[i][2] = fmaxf(acc[i][2] + cv.z + dv.z, 0.f);
        acc[i][3] = fmaxf(acc[i][3] + cv.w + dv.w, 0.f);
    }
    __syncthreads();   // all phase-1 reads of Es done before overwrite
#pragma unroll
    for (int i = 0; i < 8; i++) {
        *(float4*)&Es[(rg * 8 + i) * 128 + cg * 4] =
            make_float4(acc[i][0], acc[i][1], acc[i][2], acc[i][3]);
    }
    loadW(W2, 0, 0);
    cpa_commit();
#pragma unroll
    for (int i = 0; i < 8; i++)
#pragma unroll
        for (int j = 0; j < 4; j++) acc[i][j] = 0.f;
    __syncthreads();   // t-tile complete before phase 2 reads

    // ---- phase 2: e_new = ea + 0.5*(t @ W2 + b2) ----
    b = 0;
    for (int k0 = 0; k0 < H; k0 += 16, b ^= 1) {
        bool nxt = (k0 + 16) < H;
        if (nxt) { loadW(W2, k0 + 16, b ^ 1); cpa_commit(); }
        if (nxt) cpa_wait1(); else cpa_wait0();
        __syncthreads();
        const float* ws = &Ws[b][0];
#pragma unroll
        for (int kk = 0; kk < 16; kk++) {
            float4 w = *(const float4*)&ws[kk * 128 + cg * 4];
            float a[8];
#pragma unroll
            for (int i = 0; i < 8; i++) a[i] = Es[(rg * 8 + i) * 128 + k0 + kk];
#pragma unroll
            for (int i = 0; i < 8; i++) {
                acc[i][0] += a[i] * w.x; acc[i][1] += a[i] * w.y;
                acc[i][2] += a[i] * w.z; acc[i][3] += a[i] * w.w;
            }
        }
        __syncthreads();
    }
    float4 b4 = *(const float4*)&b2[cg * 4];
#pragma unroll
    for (int i = 0; i < 8; i++) {
        long long row = row0 + rg * 8 + i;
        if (row >= E) break;
        float4 e4 = *(const float4*)&ea[row * H + cg * 4];  // reload residual (L2)
        float4 o;
        o.x = e4.x + 0.5f * (acc[i][0] + b4.x);
        o.y = e4.y + 0.5f * (acc[i][1] + b4.y);
        o.z = e4.z + 0.5f * (acc[i][2] + b4.z);
        o.w = e4.w + 0.5f * (acc[i][3] + b4.w);
        *(float4*)&eout[row * H + cg * 4] = o;
    }
}

// ---------------- launch ----------------
extern "C" void kernel_launch(void* const* d_in, const int* in_sizes, int n_in,
                              void* d_out, int out_size) {
    const float* x     = (const float*)d_in[0];
    const float* ea    = (const float*)d_in[1];
    const float* We    = (const float*)d_in[2];
    const float* be    = (const float*)d_in[3];
    const float* Wpre  = (const float*)d_in[4];
    const float* bpre  = (const float*)d_in[5];
    const float* Wpost = (const float*)d_in[6];
    const float* bpost = (const float*)d_in[7];
    const float* Wlin  = (const float*)d_in[8];
    const float* blin  = (const float*)d_in[9];
    const float* bn_g  = (const float*)d_in[10];
    const float* bn_b  = (const float*)d_in[11];
    const float* W1    = (const float*)d_in[12];
    const float* b1    = (const float*)d_in[13];
    const float* W2    = (const float*)d_in[14];
    const float* b2    = (const float*)d_in[15];
    const int*   ei    = (const int*)d_in[16];

    int N = in_sizes[0] / H;
    int E = in_sizes[1] / H;
    const int* src = ei;
    const int* dst = ei + E;
    float* xnew = (float*)d_out;
    float* enew = (float*)d_out + (size_t)N * H;

    float *pA, *pB, *pOut, *pAgg, *pWpl, *pbpl, *pS1, *pS2, *pC, *pD;
    cudaGetSymbolAddress((void**)&pA, g_A);
    cudaGetSymbolAddress((void**)&pB, g_B);
    cudaGetSymbolAddress((void**)&pOut, g_outbuf);
    cudaGetSymbolAddress((void**)&pAgg, g_agg);
    cudaGetSymbolAddress((void**)&pWpl, g_Wpl);
    cudaGetSymbolAddress((void**)&pbpl, g_bpl);
    cudaGetSymbolAddress((void**)&pS1, g_s1);
    cudaGetSymbolAddress((void**)&pS2, g_s2);
    cudaGetSymbolAddress((void**)&pC, g_C);
    cudaGetSymbolAddress((void**)&pD, g_D);

    int gN = (N + 63) / 64;
    int gE = (E + 63) / 64;

    prep_Wc<<<H + 1, H>>>(We, be, Wpre, bpre);
    prep_Wpl<<<13 * H + 1, H>>>(Wpost, bpost, Wlin, blin);
    zero_kernel<<<(N + 255) / 256, 256>>>(N);

    // A = x @ Wpre[0:H] (dst part), B = x @ Wpre[H:2H] (src part)
    sgemm64<<<gN, 256>>>(pA, x, Wpre,          N, H, nullptr, nullptr, 0);
    sgemm64<<<gN, 256>>>(pB, x, Wpre + H * H,  N, H, nullptr, nullptr, 0);

    count_fill<<<256, 256>>>(dst, E);
    edge_h_kernel<<<gE, 256>>>(ea, src, dst, E);
    agg_kernel<<<(N + 7) / 8, 256>>>(N);

    // out = x@Wpl0 + agg@WplA + s1*(agg@WplB) + s2*(agg@WplC) + bpl
    sgemm64<<<gN, 256>>>(pOut, x,    pWpl,             N, H,     pbpl,    nullptr, 0);
    sgemm64<<<gN, 256>>>(pOut, pAgg, pWpl + 1 * H * H, N, 4 * H, nullptr, nullptr, 1);
    sgemm64<<<gN, 256>>>(pOut, pAgg, pWpl + 5 * H * H, N, 4 * H, nullptr, pS1,     1);
    sgemm64<<<gN, 256>>>(pOut, pAgg, pWpl + 9 * H * H, N, 4 * H, nullptr, pS2,     1);

    bn_stats<<<(N + 255) / 256, H>>>(N);
    bn_finalize<<<2048, 256>>>(xnew, x, bn_g, bn_b, N);

    // C = x_new @ W1[0:H] + b1 (src part), D = x_new @ W1[H:2H] (dst part)
    sgemm64<<<gN, 256>>>(pC, xnew, W1,         N, H, b1,      nullptr, 0);
    sgemm64<<<gN, 256>>>(pD, xnew, W1 + H * H, N, H, nullptr, nullptr, 0);

    edge_update<<<gE, 256>>>(enew, ea, W1 + 2 * H * H, W2, b2, src, dst, E);
}